// round 11
// baseline (speedup 1.0000x reference)
#include <cuda_runtime.h>

#define NN 4096
#define EE 16384
#define DD 13
#define RR 128
#define NP 4
#define PBLK 8
#define EPB  (EE / PBLK)
#define GCAP 2304

typedef unsigned long long u64;

__device__ int   g_groups[PBLK * GCAP];
__device__ int   g_cnt4[PBLK];
__device__ __align__(16) float g_nodes16[NN * 16];
__device__ __align__(16) float g_bpd [NP * DD * 2 * RR];      // [ty][d][2r] duplicated
__device__ __align__(16) float g_bpbd[NP * 2 * RR];           // [ty][2r]    duplicated
__device__ __align__(16) float g_hod [3 * NP * DD * 2 * RR];  // [sp][d][2r] duplicated

// k_main smem layout (floats)
#define S_BPD  0                       // 13312
#define S_BPBD 13312                   // 1024
#define S_HOD  14336                   // 39936
#define S_HOB  54272                   // 156
#define S_TOT  54428                   // 217712 bytes

// ---------------- f32x2 packed helpers --------------------------------------
__device__ __forceinline__ u64 pk2(float lo, float hi) {
    u64 r; asm("mov.b64 %0,{%1,%2};" : "=l"(r) : "f"(lo), "f"(hi)); return r;
}
__device__ __forceinline__ void up2(float& lo, float& hi, u64 v) {
    asm("mov.b64 {%0,%1},%2;" : "=f"(lo), "=f"(hi) : "l"(v));
}
__device__ __forceinline__ u64 fma2(u64 a, u64 b, u64 c) {
    u64 d; asm("fma.rn.f32x2 %0,%1,%2,%3;" : "=l"(d) : "l"(a), "l"(b), "l"(c)); return d;
}
__device__ __forceinline__ u64 mul2(u64 a, u64 b) {
    u64 d; asm("mul.rn.f32x2 %0,%1,%2;" : "=l"(d) : "l"(a), "l"(b)); return d;
}
__device__ __forceinline__ u64 add2(u64 a, u64 b) {
    u64 d; asm("add.rn.f32x2 %0,%1,%2;" : "=l"(d) : "l"(a), "l"(b)); return d;
}
__device__ __forceinline__ u64 relu2(u64 v) {
    float lo, hi; up2(lo, hi, v);
    return pk2(fmaxf(lo, 0.f), fmaxf(hi, 0.f));
}

// ---- prep: bucket sort, nodes16, zero-out, duplicated weight buffers --------
__global__ void __launch_bounds__(1024, 1) k_prep(const int* __restrict__ et,
                                                  const float* __restrict__ nodes,
                                                  const float* __restrict__ bp_params,
                                                  const float* __restrict__ bp_bias,
                                                  const float* __restrict__ ho_params,
                                                  float* __restrict__ out) {
    __shared__ int hist[64], bstart[64], cursor[64], gb[64];
    __shared__ short sorted[EPB];
    __shared__ unsigned char keys[EPB], skey[EPB];
    const int tid = threadIdx.x;
    const int bi  = blockIdx.x;
    const int base = bi * EPB;
    const int gtid = bi * 1024 + tid;

    for (int i = tid; i < NN * DD / PBLK; i += 1024) out[bi * (NN * DD / PBLK) + i] = 0.f;
    for (int i = tid; i < (NN / PBLK) * 16; i += 1024) {
        int row = i >> 4, c = i & 15;
        int gr = bi * (NN / PBLK) + row;
        g_nodes16[gr * 16 + c] = (c < DD) ? nodes[gr * DD + c] : 0.f;
    }
    // duplicated bp weights: src [ty][d][r] -> dst [ty][d][2r]{v,v}
    for (int i = gtid; i < NP * DD * RR; i += PBLK * 1024) {
        float v = bp_params[i];
        *reinterpret_cast<float2*>(g_bpd + 2 * i) = make_float2(v, v);
    }
    for (int i = gtid; i < NP * RR; i += PBLK * 1024) {
        float v = bp_bias[i];
        *reinterpret_cast<float2*>(g_bpbd + 2 * i) = make_float2(v, v);
    }
    // duplicated transposed ho: src [sp][r][d] -> dst [sp][d][2r]{v,v}
    for (int i = gtid; i < 3 * NP * RR * DD; i += PBLK * 1024) {
        int d  = i % DD;
        int r  = (i / DD) & (RR - 1);
        int sp = i / (DD * RR);
        float v = ho_params[i];
        *reinterpret_cast<float2*>(g_hod + (sp * DD + d) * 2 * RR + 2 * r) = make_float2(v, v);
    }
    for (int i = tid; i < GCAP; i += 1024) g_groups[bi * GCAP + i] = -1;

    if (tid < 64) hist[tid] = 0;
    __syncthreads();
    for (int i = tid; i < EPB; i += 1024) {
        int e = base + i;
        int k = __ldg(et + e * 3) * 16 + __ldg(et + e * 3 + 1) * 4 + __ldg(et + e * 3 + 2);
        keys[i] = (unsigned char)k;
        atomicAdd(&hist[k], 1);
    }
    __syncthreads();
    if (tid == 0) {
        int run = 0, rg = 0;
        for (int k = 0; k < 64; k++) {
            bstart[k] = run; cursor[k] = run; run += hist[k];
            gb[k] = rg; rg += (hist[k] + 3) >> 2;
        }
        g_cnt4[bi] = rg;
    }
    __syncthreads();
    for (int i = tid; i < EPB; i += 1024) {
        int k = keys[i];
        int pos = atomicAdd(&cursor[k], 1);
        sorted[pos] = (short)i;
        skey[pos] = (unsigned char)k;
    }
    __syncthreads();
    for (int i = tid; i < EPB; i += 1024) {
        int k = skey[i];
        int r = i - bstart[k];
        g_groups[bi * GCAP + gb[k] * 4 + r] = base + (int)sorted[i];
    }
}

// ---- interleaved packed warp reduction of 2x13 f32x2 streams -----------------
__device__ __forceinline__ void tree13p2(u64* a, u64* b, int lane, u64& ra, u64& rb) {
    {
        u64 oa[13], ob[13];
#pragma unroll
        for (int i = 0; i < 13; i++) { oa[i] = __shfl_xor_sync(0xffffffffu, a[i], 16);
                                       ob[i] = __shfl_xor_sync(0xffffffffu, b[i], 16); }
        if (lane & 16) {
#pragma unroll
            for (int i = 0; i < 6; i++) { a[i] = add2(a[i + 7], oa[i + 7]); b[i] = add2(b[i + 7], ob[i + 7]); }
        } else {
#pragma unroll
            for (int i = 0; i < 7; i++) { a[i] = add2(a[i], oa[i]); b[i] = add2(b[i], ob[i]); }
        }
    }
    {
        u64 oa[7], ob[7];
#pragma unroll
        for (int i = 0; i < 7; i++) { oa[i] = __shfl_xor_sync(0xffffffffu, a[i], 8);
                                      ob[i] = __shfl_xor_sync(0xffffffffu, b[i], 8); }
        if (!(lane & 16)) {
            if (lane & 8) { a[0] = add2(a[4], oa[4]); a[1] = add2(a[5], oa[5]); a[2] = add2(a[6], oa[6]);
                            b[0] = add2(b[4], ob[4]); b[1] = add2(b[5], ob[5]); b[2] = add2(b[6], ob[6]); }
            else { a[0] = add2(a[0], oa[0]); a[1] = add2(a[1], oa[1]); a[2] = add2(a[2], oa[2]); a[3] = add2(a[3], oa[3]);
                   b[0] = add2(b[0], ob[0]); b[1] = add2(b[1], ob[1]); b[2] = add2(b[2], ob[2]); b[3] = add2(b[3], ob[3]); }
        } else {
            if (lane & 8) { a[0] = add2(a[3], oa[3]); a[1] = add2(a[4], oa[4]); a[2] = add2(a[5], oa[5]);
                            b[0] = add2(b[3], ob[3]); b[1] = add2(b[4], ob[4]); b[2] = add2(b[5], ob[5]); }
            else { a[0] = add2(a[0], oa[0]); a[1] = add2(a[1], oa[1]); a[2] = add2(a[2], oa[2]);
                   b[0] = add2(b[0], ob[0]); b[1] = add2(b[1], ob[1]); b[2] = add2(b[2], ob[2]); }
        }
    }
    {
        u64 oa[4], ob[4];
#pragma unroll
        for (int i = 0; i < 4; i++) { oa[i] = __shfl_xor_sync(0xffffffffu, a[i], 4);
                                      ob[i] = __shfl_xor_sync(0xffffffffu, b[i], 4); }
        bool four = ((lane & 24) == 0);
        if (lane & 4) {
            a[0] = add2(a[2], oa[2]); b[0] = add2(b[2], ob[2]);
            if (four) { a[1] = add2(a[3], oa[3]); b[1] = add2(b[3], ob[3]); }
        } else {
            a[0] = add2(a[0], oa[0]); a[1] = add2(a[1], oa[1]);
            b[0] = add2(b[0], ob[0]); b[1] = add2(b[1], ob[1]);
        }
    }
    {
        u64 oa0 = __shfl_xor_sync(0xffffffffu, a[0], 2);
        u64 oa1 = __shfl_xor_sync(0xffffffffu, a[1], 2);
        u64 ob0 = __shfl_xor_sync(0xffffffffu, b[0], 2);
        u64 ob1 = __shfl_xor_sync(0xffffffffu, b[1], 2);
        a[0] = (lane & 2) ? add2(a[1], oa1) : add2(a[0], oa0);
        b[0] = (lane & 2) ? add2(b[1], ob1) : add2(b[0], ob0);
    }
    {
        u64 oa0 = __shfl_xor_sync(0xffffffffu, a[0], 1);
        u64 ob0 = __shfl_xor_sync(0xffffffffu, b[0], 1);
        ra = add2(a[0], oa0);
        rb = add2(b[0], ob0);
    }
}

__global__ void __launch_bounds__(512, 1) k_main(
    const float* __restrict__ ho_bias,
    const int*   __restrict__ edges,
    const int*   __restrict__ et,
    float*       __restrict__ out)
{
    extern __shared__ float sm[];
    // clean float4 copies of pre-duplicated weight buffers
    {
        const float4* s1 = reinterpret_cast<const float4*>(g_bpd);
        float4* d1 = reinterpret_cast<float4*>(sm + S_BPD);
        for (int i = threadIdx.x; i < (NP * DD * 2 * RR) / 4; i += blockDim.x) d1[i] = s1[i];
        const float4* s2 = reinterpret_cast<const float4*>(g_bpbd);
        float4* d2 = reinterpret_cast<float4*>(sm + S_BPBD);
        for (int i = threadIdx.x; i < (NP * 2 * RR) / 4; i += blockDim.x) d2[i] = s2[i];
        const float4* s3 = reinterpret_cast<const float4*>(g_hod);
        float4* d3 = reinterpret_cast<float4*>(sm + S_HOD);
        for (int i = threadIdx.x; i < (3 * NP * DD * 2 * RR) / 4; i += blockDim.x) d3[i] = s3[i];
        for (int i = threadIdx.x; i < 3 * NP * DD; i += blockDim.x) sm[S_HOB + i] = ho_bias[i];
    }
    __syncthreads();

    const int lane = threadIdx.x & 31;
    const int wid  = blockIdx.x * (blockDim.x >> 5) + (threadIdx.x >> 5);
    const int nw   = gridDim.x * (blockDim.x >> 5);

    int pre[PBLK + 1];
    pre[0] = 0;
#pragma unroll
    for (int b = 0; b < PBLK; b++) pre[b + 1] = pre[b] + __ldg(&g_cnt4[b]);
    const int total = pre[PBLK];

    const int b4 = (lane >> 4) & 1, b3 = (lane >> 3) & 1, b2 = (lane >> 2) & 1,
              b1 = (lane >> 1) & 1, b0 = lane & 1;
    const bool alive = (b0 == 0) && !(b1 && b2 && (b4 | b3));
    const int sid = 7 * b4 + (b4 ? 3 * b3 : 4 * b3) + 2 * b2 + b1;

#pragma unroll 1
    for (int u = wid; u < total; u += nw) {
        int bi = 0;
#pragma unroll
        for (int b = 1; b < PBLK; b++) bi += (u >= pre[b]);
        const int local = u - pre[bi];
        const int* gp = g_groups + bi * GCAP + local * 4;
        int ids[4];
#pragma unroll
        for (int b = 0; b < 4; b++) ids[b] = gp[b];
        int vmask = 1;
#pragma unroll
        for (int b = 1; b < 4; b++) {
            if (ids[b] >= 0) vmask |= (1 << b);
            else ids[b] = ids[0];
        }
        const int ty0 = __ldg(et + ids[0] * 3 + 0);
        const int ty1 = __ldg(et + ids[0] * 3 + 1);
        const int ty2 = __ldg(et + ids[0] * 3 + 2);
        const int ty[3] = {ty0, ty1, ty2};

        int nd[4][3];
#pragma unroll
        for (int b = 0; b < 4; b++)
#pragma unroll
            for (int s = 0; s < 3; s++)
                nd[b][s] = __ldg(edges + ids[b] * 3 + s);

        // ===== stage 1: packed accs, duplicated weights from smem ============
        u64 t01[3][4], t23[3][4];
#pragma unroll
        for (int s = 0; s < 3; s++) {
            const float* wb = sm + S_BPD + ty[s] * (DD * 2 * RR);
            const ulonglong2* bb = reinterpret_cast<const ulonglong2*>(sm + S_BPBD + ty[s] * (2 * RR) + lane * 8);
            ulonglong2 bb0 = bb[0], bb1 = bb[1];
            u64 a01[4] = {bb0.x, bb0.y, bb1.x, bb1.y};
            u64 a23[4] = {bb0.x, bb0.y, bb1.x, bb1.y};
#pragma unroll
            for (int j = 0; j < 4; j++) {
                float4 rv0 = *reinterpret_cast<const float4*>(g_nodes16 + nd[0][s] * 16 + j * 4);
                float4 rv1 = *reinterpret_cast<const float4*>(g_nodes16 + nd[1][s] * 16 + j * 4);
                float4 rv2 = *reinterpret_cast<const float4*>(g_nodes16 + nd[2][s] * 16 + j * 4);
                float4 rv3 = *reinterpret_cast<const float4*>(g_nodes16 + nd[3][s] * 16 + j * 4);
                const int dmax = (j == 3) ? 1 : 4;
#pragma unroll
                for (int dc = 0; dc < dmax; dc++) {
                    const int d = j * 4 + dc;
                    const float* wrow = wb + d * (2 * RR) + lane * 8;
                    ulonglong2 w0 = *reinterpret_cast<const ulonglong2*>(wrow);
                    ulonglong2 w1 = *reinterpret_cast<const ulonglong2*>(wrow + 4);
                    float r0 = (dc == 0) ? rv0.x : (dc == 1) ? rv0.y : (dc == 2) ? rv0.z : rv0.w;
                    float r1 = (dc == 0) ? rv1.x : (dc == 1) ? rv1.y : (dc == 2) ? rv1.z : rv1.w;
                    float r2 = (dc == 0) ? rv2.x : (dc == 1) ? rv2.y : (dc == 2) ? rv2.z : rv2.w;
                    float r3 = (dc == 0) ? rv3.x : (dc == 1) ? rv3.y : (dc == 2) ? rv3.z : rv3.w;
                    u64 rr01 = pk2(r0, r1), rr23 = pk2(r2, r3);
                    a01[0] = fma2(rr01, w0.x, a01[0]);
                    a01[1] = fma2(rr01, w0.y, a01[1]);
                    a01[2] = fma2(rr01, w1.x, a01[2]);
                    a01[3] = fma2(rr01, w1.y, a01[3]);
                    a23[0] = fma2(rr23, w0.x, a23[0]);
                    a23[1] = fma2(rr23, w0.y, a23[1]);
                    a23[2] = fma2(rr23, w1.x, a23[2]);
                    a23[3] = fma2(rr23, w1.y, a23[3]);
                }
            }
#pragma unroll
            for (int c = 0; c < 4; c++) {
                t01[s][c] = relu2(a01[c]);
                t23[s][c] = relu2(a23[c]);
            }
        }

        // ===== stage 2: packed FMA with duplicated weights + fused trees =====
#pragma unroll
        for (int s = 0; s < 3; s++) {
            const int jj = (s == 0) ? 1 : 0;
            const int kk = (s == 2) ? 1 : 2;
            u64 f01[4], f23[4];
#pragma unroll
            for (int c = 0; c < 4; c++) {
                f01[c] = mul2(t01[jj][c], t01[kk][c]);
                f23[c] = mul2(t23[jj][c], t23[kk][c]);
            }
            const float* wh = sm + S_HOD + (s * NP + ty[s]) * (DD * 2 * RR);
            const float* hb = sm + S_HOB + (s * NP + ty[s]) * DD;
            u64 ms01[DD], ms23[DD];
#pragma unroll
            for (int d = 0; d < DD; d++) {
                const float* wrow = wh + d * (2 * RR) + lane * 8;
                ulonglong2 w0 = *reinterpret_cast<const ulonglong2*>(wrow);
                ulonglong2 w1 = *reinterpret_cast<const ulonglong2*>(wrow + 4);
                u64 m0 = mul2(f01[0], w0.x);
                m0 = fma2(f01[1], w0.y, m0);
                m0 = fma2(f01[2], w1.x, m0);
                ms01[d] = fma2(f01[3], w1.y, m0);
                u64 m1 = mul2(f23[0], w0.x);
                m1 = fma2(f23[1], w0.y, m1);
                m1 = fma2(f23[2], w1.x, m1);
                ms23[d] = fma2(f23[3], w1.y, m1);
            }
            u64 r01, r23;
            tree13p2(ms01, ms23, lane, r01, r23);
            if (alive) {
                float bias = hb[sid];
                float lo, hi;
                up2(lo, hi, r01);
                atomicAdd(out + nd[0][s] * DD + sid, lo + bias);
                if (vmask & 2) atomicAdd(out + nd[1][s] * DD + sid, hi + bias);
                up2(lo, hi, r23);
                if (vmask & 4) atomicAdd(out + nd[2][s] * DD + sid, lo + bias);
                if (vmask & 8) atomicAdd(out + nd[3][s] * DD + sid, hi + bias);
            }
        }
    }
}

extern "C" void kernel_launch(void* const* d_in, const int* in_sizes, int n_in,
                              void* d_out, int out_size) {
    const float* nodes      = (const float*)d_in[0];
    const float* bp_params  = (const float*)d_in[1];
    const float* bp_bias    = (const float*)d_in[2];
    const float* ho_params  = (const float*)d_in[3];
    const float* ho_bias    = (const float*)d_in[4];
    const int*   edges      = (const int*)d_in[5];
    const int*   edge_types = (const int*)d_in[6];
    float* out = (float*)d_out;

    int sms = 0;
    cudaDeviceGetAttribute(&sms, cudaDevAttrMultiProcessorCount, 0);
    if (sms <= 0) sms = 148;
    cudaFuncSetAttribute(k_main, cudaFuncAttributeMaxDynamicSharedMemorySize, S_TOT * 4);

    k_prep<<<PBLK, 1024>>>(edge_types, nodes, bp_params, bp_bias, ho_params, out);
    k_main<<<sms, 512, S_TOT * 4>>>(ho_bias, edges, edge_types, out);
}

// round 12
// speedup vs baseline: 1.5045x; 1.5045x over previous
#include <cuda_runtime.h>

#define NN 4096
#define EE 16384
#define DD 13
#define RR 128
#define NP 4
#define HOSTRIDE 132
#define PBLK 8
#define PREPB 16
#define EPB  (EE / PBLK)
#define GCAP 2304

typedef unsigned long long u64;

__device__ int   g_groups[PBLK * GCAP];
__device__ int   g_cnt4[PBLK];
__device__ __align__(16) float g_nodes16[NN * 16];
__device__ __align__(16) float g_hoT[3 * NP * DD * HOSTRIDE];

// k_main smem layout (floats)
#define S_BP   0
#define S_BPB  (NP * DD * RR)
#define S_HO   (S_BPB + NP * RR)
#define S_HOB  (S_HO + 3 * NP * DD * HOSTRIDE)
#define S_TOT  (S_HOB + 3 * NP * DD)   // ~109.1 KiB

// ---------------- f32x2 packed helpers --------------------------------------
__device__ __forceinline__ u64 pk2(float lo, float hi) {
    u64 r; asm("mov.b64 %0,{%1,%2};" : "=l"(r) : "f"(lo), "f"(hi)); return r;
}
__device__ __forceinline__ u64 dup2(float v) {
    u64 r; asm("mov.b64 %0,{%1,%1};" : "=l"(r) : "f"(v)); return r;
}
__device__ __forceinline__ void up2(float& lo, float& hi, u64 v) {
    asm("mov.b64 {%0,%1},%2;" : "=f"(lo), "=f"(hi) : "l"(v));
}
__device__ __forceinline__ u64 fma2(u64 a, u64 b, u64 c) {
    u64 d; asm("fma.rn.f32x2 %0,%1,%2,%3;" : "=l"(d) : "l"(a), "l"(b), "l"(c)); return d;
}
__device__ __forceinline__ u64 mul2(u64 a, u64 b) {
    u64 d; asm("mul.rn.f32x2 %0,%1,%2;" : "=l"(d) : "l"(a), "l"(b)); return d;
}
__device__ __forceinline__ u64 add2(u64 a, u64 b) {
    u64 d; asm("add.rn.f32x2 %0,%1,%2;" : "=l"(d) : "l"(a), "l"(b)); return d;
}
__device__ __forceinline__ u64 relu2(u64 v) {
    float lo, hi; up2(lo, hi, v);
    return pk2(fmaxf(lo, 0.f), fmaxf(hi, 0.f));
}

// ---- prep (16 blocks): blocks 0-7 bucket-sort their region; all 16 share
//      the zero/nodes16/hoT-transpose copy jobs ------------------------------
__global__ void __launch_bounds__(1024, 1) k_prep(const int* __restrict__ et,
                                                  const float* __restrict__ nodes,
                                                  const float* __restrict__ ho_params,
                                                  float* __restrict__ out) {
    __shared__ int hist[64], bstart[64], cursor[64], gb[64];
    __shared__ short sorted[EPB];
    __shared__ unsigned char keys[EPB], skey[EPB];
    const int tid = threadIdx.x;
    const int bi  = blockIdx.x;

    // shared copy jobs, split over all 16 blocks
    for (int i = tid; i < NN * DD / PREPB; i += 1024) out[bi * (NN * DD / PREPB) + i] = 0.f;
    for (int i = tid; i < (NN / PREPB) * 16; i += 1024) {
        int row = i >> 4, c = i & 15;
        int gr = bi * (NN / PREPB) + row;
        g_nodes16[gr * 16 + c] = (c < DD) ? nodes[gr * DD + c] : 0.f;
    }
    {
        const int totalho = 3 * NP * RR * DD;   // 19968
        for (int i = bi * 1024 + tid; i < totalho; i += PREPB * 1024) {
            int d  = i % DD;
            int rd = i / DD;
            int r  = rd & (RR - 1);
            int sp = rd >> 7;
            g_hoT[(sp * DD + d) * HOSTRIDE + r] = ho_params[i];
        }
    }

    if (bi >= PBLK) return;
    const int base = bi * EPB;
    for (int i = tid; i < GCAP; i += 1024) g_groups[bi * GCAP + i] = -1;

    if (tid < 64) hist[tid] = 0;
    __syncthreads();
    for (int i = tid; i < EPB; i += 1024) {
        int e = base + i;
        int k = __ldg(et + e * 3) * 16 + __ldg(et + e * 3 + 1) * 4 + __ldg(et + e * 3 + 2);
        keys[i] = (unsigned char)k;
        atomicAdd(&hist[k], 1);
    }
    __syncthreads();
    if (tid == 0) {
        int run = 0, rg = 0;
        for (int k = 0; k < 64; k++) {
            bstart[k] = run; cursor[k] = run; run += hist[k];
            gb[k] = rg; rg += (hist[k] + 3) >> 2;
        }
        g_cnt4[bi] = rg;
    }
    __syncthreads();
    for (int i = tid; i < EPB; i += 1024) {
        int k = keys[i];
        int pos = atomicAdd(&cursor[k], 1);
        sorted[pos] = (short)i;
        skey[pos] = (unsigned char)k;
    }
    __syncthreads();
    for (int i = tid; i < EPB; i += 1024) {
        int k = skey[i];
        int r = i - bstart[k];
        g_groups[bi * GCAP + gb[k] * 4 + r] = base + (int)sorted[i];
    }
}

// ---- interleaved packed warp reduction of 2x13 f32x2 streams ----------------
__device__ __forceinline__ void tree13p2(u64* a, u64* b, int lane, u64& ra, u64& rb) {
    {
        u64 oa[13], ob[13];
#pragma unroll
        for (int i = 0; i < 13; i++) { oa[i] = __shfl_xor_sync(0xffffffffu, a[i], 16);
                                       ob[i] = __shfl_xor_sync(0xffffffffu, b[i], 16); }
        if (lane & 16) {
#pragma unroll
            for (int i = 0; i < 6; i++) { a[i] = add2(a[i + 7], oa[i + 7]); b[i] = add2(b[i + 7], ob[i + 7]); }
        } else {
#pragma unroll
            for (int i = 0; i < 7; i++) { a[i] = add2(a[i], oa[i]); b[i] = add2(b[i], ob[i]); }
        }
    }
    {
        u64 oa[7], ob[7];
#pragma unroll
        for (int i = 0; i < 7; i++) { oa[i] = __shfl_xor_sync(0xffffffffu, a[i], 8);
                                      ob[i] = __shfl_xor_sync(0xffffffffu, b[i], 8); }
        if (!(lane & 16)) {
            if (lane & 8) { a[0] = add2(a[4], oa[4]); a[1] = add2(a[5], oa[5]); a[2] = add2(a[6], oa[6]);
                            b[0] = add2(b[4], ob[4]); b[1] = add2(b[5], ob[5]); b[2] = add2(b[6], ob[6]); }
            else { a[0] = add2(a[0], oa[0]); a[1] = add2(a[1], oa[1]); a[2] = add2(a[2], oa[2]); a[3] = add2(a[3], oa[3]);
                   b[0] = add2(b[0], ob[0]); b[1] = add2(b[1], ob[1]); b[2] = add2(b[2], ob[2]); b[3] = add2(b[3], ob[3]); }
        } else {
            if (lane & 8) { a[0] = add2(a[3], oa[3]); a[1] = add2(a[4], oa[4]); a[2] = add2(a[5], oa[5]);
                            b[0] = add2(b[3], ob[3]); b[1] = add2(b[4], ob[4]); b[2] = add2(b[5], ob[5]); }
            else { a[0] = add2(a[0], oa[0]); a[1] = add2(a[1], oa[1]); a[2] = add2(a[2], oa[2]);
                   b[0] = add2(b[0], ob[0]); b[1] = add2(b[1], ob[1]); b[2] = add2(b[2], ob[2]); }
        }
    }
    {
        u64 oa[4], ob[4];
#pragma unroll
        for (int i = 0; i < 4; i++) { oa[i] = __shfl_xor_sync(0xffffffffu, a[i], 4);
                                      ob[i] = __shfl_xor_sync(0xffffffffu, b[i], 4); }
        bool four = ((lane & 24) == 0);
        if (lane & 4) {
            a[0] = add2(a[2], oa[2]); b[0] = add2(b[2], ob[2]);
            if (four) { a[1] = add2(a[3], oa[3]); b[1] = add2(b[3], ob[3]); }
        } else {
            a[0] = add2(a[0], oa[0]); a[1] = add2(a[1], oa[1]);
            b[0] = add2(b[0], ob[0]); b[1] = add2(b[1], ob[1]);
        }
    }
    {
        u64 oa0 = __shfl_xor_sync(0xffffffffu, a[0], 2);
        u64 oa1 = __shfl_xor_sync(0xffffffffu, a[1], 2);
        u64 ob0 = __shfl_xor_sync(0xffffffffu, b[0], 2);
        u64 ob1 = __shfl_xor_sync(0xffffffffu, b[1], 2);
        a[0] = (lane & 2) ? add2(a[1], oa1) : add2(a[0], oa0);
        b[0] = (lane & 2) ? add2(b[1], ob1) : add2(b[0], ob0);
    }
    {
        u64 oa0 = __shfl_xor_sync(0xffffffffu, a[0], 1);
        u64 ob0 = __shfl_xor_sync(0xffffffffu, b[0], 1);
        ra = add2(a[0], oa0);
        rb = add2(b[0], ob0);
    }
}

__global__ void __launch_bounds__(512, 1) k_main(
    const float* __restrict__ bp_params,
    const float* __restrict__ bp_bias,
    const float* __restrict__ ho_bias,
    const int*   __restrict__ edges,
    const int*   __restrict__ et,
    float*       __restrict__ out)
{
    extern __shared__ float sm[];
    for (int i = threadIdx.x; i < NP * DD * RR; i += blockDim.x) sm[S_BP + i] = bp_params[i];
    for (int i = threadIdx.x; i < NP * RR; i += blockDim.x)      sm[S_BPB + i] = bp_bias[i];
    {   // clean float4 copy of pre-transposed HO weights
        const float4* src = reinterpret_cast<const float4*>(g_hoT);
        float4* dst = reinterpret_cast<float4*>(sm + S_HO);
        for (int i = threadIdx.x; i < (3 * NP * DD * HOSTRIDE) / 4; i += blockDim.x) dst[i] = src[i];
    }
    for (int i = threadIdx.x; i < 3 * NP * DD; i += blockDim.x)  sm[S_HOB + i] = ho_bias[i];
    __syncthreads();

    const int lane = threadIdx.x & 31;
    const int wid  = blockIdx.x * (blockDim.x >> 5) + (threadIdx.x >> 5);
    const int nw   = gridDim.x * (blockDim.x >> 5);

    int pre[PBLK + 1];
    pre[0] = 0;
#pragma unroll
    for (int b = 0; b < PBLK; b++) pre[b + 1] = pre[b] + __ldg(&g_cnt4[b]);
    const int total = pre[PBLK];

    const int b4 = (lane >> 4) & 1, b3 = (lane >> 3) & 1, b2 = (lane >> 2) & 1,
              b1 = (lane >> 1) & 1, b0 = lane & 1;
    const bool alive = (b0 == 0) && !(b1 && b2 && (b4 | b3));
    const int sid = 7 * b4 + (b4 ? 3 * b3 : 4 * b3) + 2 * b2 + b1;

#pragma unroll 1
    for (int u = wid; u < total; u += nw) {
        int bi = 0;
#pragma unroll
        for (int b = 1; b < PBLK; b++) bi += (u >= pre[b]);
        const int local = u - pre[bi];
        const int* gp = g_groups + bi * GCAP + local * 4;
        int ids[4];
#pragma unroll
        for (int b = 0; b < 4; b++) ids[b] = gp[b];
        int vmask = 1;
#pragma unroll
        for (int b = 1; b < 4; b++) {
            if (ids[b] >= 0) vmask |= (1 << b);
            else ids[b] = ids[0];
        }
        const int ty0 = __ldg(et + ids[0] * 3 + 0);
        const int ty1 = __ldg(et + ids[0] * 3 + 1);
        const int ty2 = __ldg(et + ids[0] * 3 + 2);
        const int ty[3] = {ty0, ty1, ty2};

        int nd[4][3];
#pragma unroll
        for (int b = 0; b < 4; b++)
#pragma unroll
            for (int s = 0; s < 3; s++)
                nd[b][s] = __ldg(edges + ids[b] * 3 + s);

        // ===== stage 1: packed accumulators over edge pairs ==================
        u64 t01[3][4], t23[3][4];
#pragma unroll
        for (int s = 0; s < 3; s++) {
            const float* wb = sm + S_BP + ty[s] * DD * RR;
            float4 bias = reinterpret_cast<const float4*>(sm + S_BPB + ty[s] * RR)[lane];
            u64 a01[4], a23[4];
            a01[0] = dup2(bias.x); a01[1] = dup2(bias.y);
            a01[2] = dup2(bias.z); a01[3] = dup2(bias.w);
            a23[0] = a01[0]; a23[1] = a01[1]; a23[2] = a01[2]; a23[3] = a01[3];
#pragma unroll
            for (int j = 0; j < 4; j++) {
                float4 rv0 = *reinterpret_cast<const float4*>(g_nodes16 + nd[0][s] * 16 + j * 4);
                float4 rv1 = *reinterpret_cast<const float4*>(g_nodes16 + nd[1][s] * 16 + j * 4);
                float4 rv2 = *reinterpret_cast<const float4*>(g_nodes16 + nd[2][s] * 16 + j * 4);
                float4 rv3 = *reinterpret_cast<const float4*>(g_nodes16 + nd[3][s] * 16 + j * 4);
                const int dmax = (j == 3) ? 1 : 4;
#pragma unroll
                for (int dc = 0; dc < dmax; dc++) {
                    const int d = j * 4 + dc;
                    float4 w = reinterpret_cast<const float4*>(wb + d * RR)[lane];
                    float r0 = (dc == 0) ? rv0.x : (dc == 1) ? rv0.y : (dc == 2) ? rv0.z : rv0.w;
                    float r1 = (dc == 0) ? rv1.x : (dc == 1) ? rv1.y : (dc == 2) ? rv1.z : rv1.w;
                    float r2 = (dc == 0) ? rv2.x : (dc == 1) ? rv2.y : (dc == 2) ? rv2.z : rv2.w;
                    float r3 = (dc == 0) ? rv3.x : (dc == 1) ? rv3.y : (dc == 2) ? rv3.z : rv3.w;
                    u64 rr01 = pk2(r0, r1), rr23 = pk2(r2, r3);
                    u64 wx = dup2(w.x), wy = dup2(w.y), wz = dup2(w.z), ww = dup2(w.w);
                    a01[0] = fma2(rr01, wx, a01[0]);
                    a01[1] = fma2(rr01, wy, a01[1]);
                    a01[2] = fma2(rr01, wz, a01[2]);
                    a01[3] = fma2(rr01, ww, a01[3]);
                    a23[0] = fma2(rr23, wx, a23[0]);
                    a23[1] = fma2(rr23, wy, a23[1]);
                    a23[2] = fma2(rr23, wz, a23[2]);
                    a23[3] = fma2(rr23, ww, a23[3]);
                }
            }
#pragma unroll
            for (int c = 0; c < 4; c++) {
                t01[s][c] = relu2(a01[c]);
                t23[s][c] = relu2(a23[c]);
            }
        }

        // ===== stage 2: packed FMA + interleaved trees =======================
#pragma unroll
        for (int s = 0; s < 3; s++) {
            const int jj = (s == 0) ? 1 : 0;
            const int kk = (s == 2) ? 1 : 2;
            u64 f01[4], f23[4];
#pragma unroll
            for (int c = 0; c < 4; c++) {
                f01[c] = mul2(t01[jj][c], t01[kk][c]);
                f23[c] = mul2(t23[jj][c], t23[kk][c]);
            }
            const float* wh = sm + S_HO + (s * NP + ty[s]) * DD * HOSTRIDE;
            const float* hb = sm + S_HOB + (s * NP + ty[s]) * DD;
            u64 ms01[DD], ms23[DD];
#pragma unroll
            for (int d = 0; d < DD; d++) {
                float4 w = reinterpret_cast<const float4*>(wh + d * HOSTRIDE)[lane];
                u64 wx = dup2(w.x), wy = dup2(w.y), wz = dup2(w.z), ww = dup2(w.w);
                u64 m0 = mul2(f01[0], wx);
                m0 = fma2(f01[1], wy, m0);
                m0 = fma2(f01[2], wz, m0);
                ms01[d] = fma2(f01[3], ww, m0);
                u64 m1 = mul2(f23[0], wx);
                m1 = fma2(f23[1], wy, m1);
                m1 = fma2(f23[2], wz, m1);
                ms23[d] = fma2(f23[3], ww, m1);
            }
            u64 r01, r23;
            tree13p2(ms01, ms23, lane, r01, r23);
            if (alive) {
                float bias = hb[sid];
                float lo, hi;
                up2(lo, hi, r01);
                atomicAdd(out + nd[0][s] * DD + sid, lo + bias);
                if (vmask & 2) atomicAdd(out + nd[1][s] * DD + sid, hi + bias);
                up2(lo, hi, r23);
                if (vmask & 4) atomicAdd(out + nd[2][s] * DD + sid, lo + bias);
                if (vmask & 8) atomicAdd(out + nd[3][s] * DD + sid, hi + bias);
            }
        }
    }
}

extern "C" void kernel_launch(void* const* d_in, const int* in_sizes, int n_in,
                              void* d_out, int out_size) {
    const float* nodes      = (const float*)d_in[0];
    const float* bp_params  = (const float*)d_in[1];
    const float* bp_bias    = (const float*)d_in[2];
    const float* ho_params  = (const float*)d_in[3];
    const float* ho_bias    = (const float*)d_in[4];
    const int*   edges      = (const int*)d_in[5];
    const int*   edge_types = (const int*)d_in[6];
    float* out = (float*)d_out;

    int sms = 0;
    cudaDeviceGetAttribute(&sms, cudaDevAttrMultiProcessorCount, 0);
    if (sms <= 0) sms = 148;
    cudaFuncSetAttribute(k_main, cudaFuncAttributeMaxDynamicSharedMemorySize, S_TOT * 4);

    k_prep<<<PREPB, 1024>>>(edge_types, nodes, ho_params, out);
    k_main<<<sms, 512, S_TOT * 4>>>(bp_params, bp_bias, ho_bias, edges, edge_types, out);
}

// round 13
// speedup vs baseline: 1.5154x; 1.0072x over previous
#include <cuda_runtime.h>

#define NN 4096
#define EE 16384
#define DD 13
#define RR 128
#define NP 4
#define HOSTRIDE 132
#define PBLK 8
#define PREPB 16
#define EPB  (EE / PBLK)
#define GCAP 2304
#define NTHR 640

typedef unsigned long long u64;

__device__ int   g_groups[PBLK * GCAP];
__device__ int   g_cnt4[PBLK];
__device__ __align__(16) float g_nodes16[NN * 16];
__device__ __align__(16) float g_hoT[3 * NP * DD * HOSTRIDE];

// k_main smem layout (floats)
#define S_BP   0
#define S_BPB  (NP * DD * RR)
#define S_HO   (S_BPB + NP * RR)
#define S_HOB  (S_HO + 3 * NP * DD * HOSTRIDE)
#define S_TOT  (S_HOB + 3 * NP * DD)   // ~109.1 KiB

// ---------------- f32x2 packed helpers --------------------------------------
__device__ __forceinline__ u64 pk2(float lo, float hi) {
    u64 r; asm("mov.b64 %0,{%1,%2};" : "=l"(r) : "f"(lo), "f"(hi)); return r;
}
__device__ __forceinline__ u64 dup2(float v) {
    u64 r; asm("mov.b64 %0,{%1,%1};" : "=l"(r) : "f"(v)); return r;
}
__device__ __forceinline__ void up2(float& lo, float& hi, u64 v) {
    asm("mov.b64 {%0,%1},%2;" : "=f"(lo), "=f"(hi) : "l"(v));
}
__device__ __forceinline__ u64 fma2(u64 a, u64 b, u64 c) {
    u64 d; asm("fma.rn.f32x2 %0,%1,%2,%3;" : "=l"(d) : "l"(a), "l"(b), "l"(c)); return d;
}
__device__ __forceinline__ u64 mul2(u64 a, u64 b) {
    u64 d; asm("mul.rn.f32x2 %0,%1,%2;" : "=l"(d) : "l"(a), "l"(b)); return d;
}
__device__ __forceinline__ u64 add2(u64 a, u64 b) {
    u64 d; asm("add.rn.f32x2 %0,%1,%2;" : "=l"(d) : "l"(a), "l"(b)); return d;
}
__device__ __forceinline__ u64 relu2(u64 v) {
    float lo, hi; up2(lo, hi, v);
    return pk2(fmaxf(lo, 0.f), fmaxf(hi, 0.f));
}

// ---- prep (16 blocks): blocks 0-7 bucket-sort their region; all 16 share
//      zero/nodes16/hoT copy jobs; parallel 64-key scan -----------------------
__global__ void __launch_bounds__(1024, 1) k_prep(const int* __restrict__ et,
                                                  const float* __restrict__ nodes,
                                                  const float* __restrict__ ho_params,
                                                  float* __restrict__ out) {
    __shared__ int hist[64], bstart[64], cursor[64], gb[64];
    __shared__ int sc[64], sg[64];
    __shared__ short sorted[EPB];
    __shared__ unsigned char keys[EPB], skey[EPB];
    const int tid = threadIdx.x;
    const int bi  = blockIdx.x;

    for (int i = tid; i < NN * DD / PREPB; i += 1024) out[bi * (NN * DD / PREPB) + i] = 0.f;
    for (int i = tid; i < (NN / PREPB) * 16; i += 1024) {
        int row = i >> 4, c = i & 15;
        int gr = bi * (NN / PREPB) + row;
        g_nodes16[gr * 16 + c] = (c < DD) ? nodes[gr * DD + c] : 0.f;
    }
    {
        const int totalho = 3 * NP * RR * DD;   // 19968
        for (int i = bi * 1024 + tid; i < totalho; i += PREPB * 1024) {
            int d  = i % DD;
            int rd = i / DD;
            int r  = rd & (RR - 1);
            int sp = rd >> 7;
            g_hoT[(sp * DD + d) * HOSTRIDE + r] = ho_params[i];
        }
    }

    if (bi >= PBLK) return;
    const int base = bi * EPB;
    for (int i = tid; i < GCAP; i += 1024) g_groups[bi * GCAP + i] = -1;

    if (tid < 64) hist[tid] = 0;
    __syncthreads();
    for (int i = tid; i < EPB; i += 1024) {
        int e = base + i;
        int k = __ldg(et + e * 3) * 16 + __ldg(et + e * 3 + 1) * 4 + __ldg(et + e * 3 + 2);
        keys[i] = (unsigned char)k;
        atomicAdd(&hist[k], 1);
    }
    __syncthreads();
    // parallel inclusive scan over 64 buckets (edges and group counts)
    if (tid < 64) { sc[tid] = hist[tid]; sg[tid] = (hist[tid] + 3) >> 2; }
    __syncthreads();
    for (int off = 1; off < 64; off <<= 1) {
        int v1 = 0, v2 = 0;
        if (tid >= off && tid < 64) { v1 = sc[tid - off]; v2 = sg[tid - off]; }
        __syncthreads();
        if (tid >= off && tid < 64) { sc[tid] += v1; sg[tid] += v2; }
        __syncthreads();
    }
    if (tid < 64) {
        bstart[tid] = sc[tid] - hist[tid];
        cursor[tid] = sc[tid] - hist[tid];
        gb[tid]     = sg[tid] - ((hist[tid] + 3) >> 2);
        if (tid == 63) g_cnt4[bi] = sg[63];
    }
    __syncthreads();
    for (int i = tid; i < EPB; i += 1024) {
        int k = keys[i];
        int pos = atomicAdd(&cursor[k], 1);
        sorted[pos] = (short)i;
        skey[pos] = (unsigned char)k;
    }
    __syncthreads();
    for (int i = tid; i < EPB; i += 1024) {
        int k = skey[i];
        int r = i - bstart[k];
        g_groups[bi * GCAP + gb[k] * 4 + r] = base + (int)sorted[i];
    }
}

// ---- tail of the interleaved packed reduction: levels xor8..xor1 on
//      pre-folded arrays of 7 (low lanes: streams 0-6; high lanes: 7-12) -----
__device__ __forceinline__ void tree_tail_p2(u64* a, u64* b, int lane, u64& ra, u64& rb) {
    {
        u64 oa[7], ob[7];
#pragma unroll
        for (int i = 0; i < 7; i++) { oa[i] = __shfl_xor_sync(0xffffffffu, a[i], 8);
                                      ob[i] = __shfl_xor_sync(0xffffffffu, b[i], 8); }
        if (!(lane & 16)) {
            if (lane & 8) { a[0] = add2(a[4], oa[4]); a[1] = add2(a[5], oa[5]); a[2] = add2(a[6], oa[6]);
                            b[0] = add2(b[4], ob[4]); b[1] = add2(b[5], ob[5]); b[2] = add2(b[6], ob[6]); }
            else { a[0] = add2(a[0], oa[0]); a[1] = add2(a[1], oa[1]); a[2] = add2(a[2], oa[2]); a[3] = add2(a[3], oa[3]);
                   b[0] = add2(b[0], ob[0]); b[1] = add2(b[1], ob[1]); b[2] = add2(b[2], ob[2]); b[3] = add2(b[3], ob[3]); }
        } else {
            if (lane & 8) { a[0] = add2(a[3], oa[3]); a[1] = add2(a[4], oa[4]); a[2] = add2(a[5], oa[5]);
                            b[0] = add2(b[3], ob[3]); b[1] = add2(b[4], ob[4]); b[2] = add2(b[5], ob[5]); }
            else { a[0] = add2(a[0], oa[0]); a[1] = add2(a[1], oa[1]); a[2] = add2(a[2], oa[2]);
                   b[0] = add2(b[0], ob[0]); b[1] = add2(b[1], ob[1]); b[2] = add2(b[2], ob[2]); }
        }
    }
    {
        u64 oa[4], ob[4];
#pragma unroll
        for (int i = 0; i < 4; i++) { oa[i] = __shfl_xor_sync(0xffffffffu, a[i], 4);
                                      ob[i] = __shfl_xor_sync(0xffffffffu, b[i], 4); }
        bool four = ((lane & 24) == 0);
        if (lane & 4) {
            a[0] = add2(a[2], oa[2]); b[0] = add2(b[2], ob[2]);
            if (four) { a[1] = add2(a[3], oa[3]); b[1] = add2(b[3], ob[3]); }
        } else {
            a[0] = add2(a[0], oa[0]); a[1] = add2(a[1], oa[1]);
            b[0] = add2(b[0], ob[0]); b[1] = add2(b[1], ob[1]);
        }
    }
    {
        u64 oa0 = __shfl_xor_sync(0xffffffffu, a[0], 2);
        u64 oa1 = __shfl_xor_sync(0xffffffffu, a[1], 2);
        u64 ob0 = __shfl_xor_sync(0xffffffffu, b[0], 2);
        u64 ob1 = __shfl_xor_sync(0xffffffffu, b[1], 2);
        a[0] = (lane & 2) ? add2(a[1], oa1) : add2(a[0], oa0);
        b[0] = (lane & 2) ? add2(b[1], ob1) : add2(b[0], ob0);
    }
    {
        u64 oa0 = __shfl_xor_sync(0xffffffffu, a[0], 1);
        u64 ob0 = __shfl_xor_sync(0xffffffffu, b[0], 1);
        ra = add2(a[0], oa0);
        rb = add2(b[0], ob0);
    }
}

__global__ void __launch_bounds__(NTHR, 1) k_main(
    const float* __restrict__ bp_params,
    const float* __restrict__ bp_bias,
    const float* __restrict__ ho_bias,
    const int*   __restrict__ edges,
    const int*   __restrict__ et,
    float*       __restrict__ out)
{
    extern __shared__ float sm[];
    for (int i = threadIdx.x; i < NP * DD * RR; i += blockDim.x) sm[S_BP + i] = bp_params[i];
    for (int i = threadIdx.x; i < NP * RR; i += blockDim.x)      sm[S_BPB + i] = bp_bias[i];
    {
        const float4* src = reinterpret_cast<const float4*>(g_hoT);
        float4* dst = reinterpret_cast<float4*>(sm + S_HO);
        for (int i = threadIdx.x; i < (3 * NP * DD * HOSTRIDE) / 4; i += blockDim.x) dst[i] = src[i];
    }
    for (int i = threadIdx.x; i < 3 * NP * DD; i += blockDim.x)  sm[S_HOB + i] = ho_bias[i];
    __syncthreads();

    const int lane = threadIdx.x & 31;
    const int warp = threadIdx.x >> 5;

    int pre[PBLK + 1];
    pre[0] = 0;
#pragma unroll
    for (int b = 0; b < PBLK; b++) pre[b + 1] = pre[b] + __ldg(&g_cnt4[b]);
    const int total = pre[PBLK];

    // block-contiguous group range for SM-level balance
    const int per = (total + gridDim.x - 1) / gridDim.x;
    const int u0 = blockIdx.x * per;
    int u1 = u0 + per; if (u1 > total) u1 = total;

    const int b4 = (lane >> 4) & 1, b3 = (lane >> 3) & 1, b2 = (lane >> 2) & 1,
              b1 = (lane >> 1) & 1, b0 = lane & 1;
    const bool alive = (b0 == 0) && !(b1 && b2 && (b4 | b3));
    const int sid = 7 * b4 + (b4 ? 3 * b3 : 4 * b3) + 2 * b2 + b1;

#pragma unroll 1
    for (int u = u0 + warp; u < u1; u += (NTHR >> 5)) {
        int bi = 0;
#pragma unroll
        for (int b = 1; b < PBLK; b++) bi += (u >= pre[b]);
        const int local = u - pre[bi];
        const int* gp = g_groups + bi * GCAP + local * 4;
        int ids[4];
#pragma unroll
        for (int b = 0; b < 4; b++) ids[b] = gp[b];
        int vmask = 1;
#pragma unroll
        for (int b = 1; b < 4; b++) {
            if (ids[b] >= 0) vmask |= (1 << b);
            else ids[b] = ids[0];
        }
        const int ty0 = __ldg(et + ids[0] * 3 + 0);
        const int ty1 = __ldg(et + ids[0] * 3 + 1);
        const int ty2 = __ldg(et + ids[0] * 3 + 2);
        const int ty[3] = {ty0, ty1, ty2};

        int nd[4][3];
#pragma unroll
        for (int b = 0; b < 4; b++)
#pragma unroll
            for (int s = 0; s < 3; s++)
                nd[b][s] = __ldg(edges + ids[b] * 3 + s);

        // ===== stage 1: packed accumulators over edge pairs ==================
        u64 t01[3][4], t23[3][4];
#pragma unroll
        for (int s = 0; s < 3; s++) {
            const float* wb = sm + S_BP + ty[s] * DD * RR;
            float4 bias = reinterpret_cast<const float4*>(sm + S_BPB + ty[s] * RR)[lane];
            u64 a01[4], a23[4];
            a01[0] = dup2(bias.x); a01[1] = dup2(bias.y);
            a01[2] = dup2(bias.z); a01[3] = dup2(bias.w);
            a23[0] = a01[0]; a23[1] = a01[1]; a23[2] = a01[2]; a23[3] = a01[3];
#pragma unroll
            for (int j = 0; j < 4; j++) {
                float4 rv0 = *reinterpret_cast<const float4*>(g_nodes16 + nd[0][s] * 16 + j * 4);
                float4 rv1 = *reinterpret_cast<const float4*>(g_nodes16 + nd[1][s] * 16 + j * 4);
                float4 rv2 = *reinterpret_cast<const float4*>(g_nodes16 + nd[2][s] * 16 + j * 4);
                float4 rv3 = *reinterpret_cast<const float4*>(g_nodes16 + nd[3][s] * 16 + j * 4);
                const int dmax = (j == 3) ? 1 : 4;
#pragma unroll
                for (int dc = 0; dc < dmax; dc++) {
                    const int d = j * 4 + dc;
                    float4 w = reinterpret_cast<const float4*>(wb + d * RR)[lane];
                    float r0 = (dc == 0) ? rv0.x : (dc == 1) ? rv0.y : (dc == 2) ? rv0.z : rv0.w;
                    float r1 = (dc == 0) ? rv1.x : (dc == 1) ? rv1.y : (dc == 2) ? rv1.z : rv1.w;
                    float r2 = (dc == 0) ? rv2.x : (dc == 1) ? rv2.y : (dc == 2) ? rv2.z : rv2.w;
                    float r3 = (dc == 0) ? rv3.x : (dc == 1) ? rv3.y : (dc == 2) ? rv3.z : rv3.w;
                    u64 rr01 = pk2(r0, r1), rr23 = pk2(r2, r3);
                    u64 wx = dup2(w.x), wy = dup2(w.y), wz = dup2(w.z), ww = dup2(w.w);
                    a01[0] = fma2(rr01, wx, a01[0]);
                    a01[1] = fma2(rr01, wy, a01[1]);
                    a01[2] = fma2(rr01, wz, a01[2]);
                    a01[3] = fma2(rr01, ww, a01[3]);
                    a23[0] = fma2(rr23, wx, a23[0]);
                    a23[1] = fma2(rr23, wy, a23[1]);
                    a23[2] = fma2(rr23, wz, a23[2]);
                    a23[3] = fma2(rr23, ww, a23[3]);
                }
            }
#pragma unroll
            for (int c = 0; c < 4; c++) {
                t01[s][c] = relu2(a01[c]);
                t23[s][c] = relu2(a23[c]);
            }
        }

        // ===== stage 2: packed FMA + in-loop level-1 fold + tail trees =======
#pragma unroll
        for (int s = 0; s < 3; s++) {
            const int jj = (s == 0) ? 1 : 0;
            const int kk = (s == 2) ? 1 : 2;
            u64 f01[4], f23[4];
#pragma unroll
            for (int c = 0; c < 4; c++) {
                f01[c] = mul2(t01[jj][c], t01[kk][c]);
                f23[c] = mul2(t23[jj][c], t23[kk][c]);
            }
            const float* wh = sm + S_HO + (s * NP + ty[s]) * DD * HOSTRIDE;
            const float* hb = sm + S_HOB + (s * NP + ty[s]) * DD;
            u64 c01[7], c23[7];
            const bool hi = (lane & 16) != 0;
#pragma unroll
            for (int d = 0; d < DD; d++) {
                float4 w = reinterpret_cast<const float4*>(wh + d * HOSTRIDE)[lane];
                u64 wx = dup2(w.x), wy = dup2(w.y), wz = dup2(w.z), ww = dup2(w.w);
                u64 m0 = mul2(f01[0], wx);
                m0 = fma2(f01[1], wy, m0);
                m0 = fma2(f01[2], wz, m0);
                m0 = fma2(f01[3], ww, m0);
                u64 m1 = mul2(f23[0], wx);
                m1 = fma2(f23[1], wy, m1);
                m1 = fma2(f23[2], wz, m1);
                m1 = fma2(f23[3], ww, m1);
                // level-1 fold (xor 16): low lanes keep d<7 at slot d,
                // high lanes keep d>=7 at slot d-7
                u64 o0 = __shfl_xor_sync(0xffffffffu, m0, 16);
                u64 o1 = __shfl_xor_sync(0xffffffffu, m1, 16);
                if (d < 7) {
                    if (!hi) { c01[d] = add2(m0, o0); c23[d] = add2(m1, o1); }
                } else {
                    if (hi)  { c01[d - 7] = add2(m0, o0); c23[d - 7] = add2(m1, o1); }
                }
            }
            u64 r01, r23;
            tree_tail_p2(c01, c23, lane, r01, r23);
            if (alive) {
                float bias = hb[sid];
                float lo, hif;
                up2(lo, hif, r01);
                atomicAdd(out + nd[0][s] * DD + sid, lo + bias);
                if (vmask & 2) atomicAdd(out + nd[1][s] * DD + sid, hif + bias);
                up2(lo, hif, r23);
                if (vmask & 4) atomicAdd(out + nd[2][s] * DD + sid, lo + bias);
                if (vmask & 8) atomicAdd(out + nd[3][s] * DD + sid, hif + bias);
            }
        }
    }
}

extern "C" void kernel_launch(void* const* d_in, const int* in_sizes, int n_in,
                              void* d_out, int out_size) {
    const float* nodes      = (const float*)d_in[0];
    const float* bp_params  = (const float*)d_in[1];
    const float* bp_bias    = (const float*)d_in[2];
    const float* ho_params  = (const float*)d_in[3];
    const float* ho_bias    = (const float*)d_in[4];
    const int*   edges      = (const int*)d_in[5];
    const int*   edge_types = (const int*)d_in[6];
    float* out = (float*)d_out;

    int sms = 0;
    cudaDeviceGetAttribute(&sms, cudaDevAttrMultiProcessorCount, 0);
    if (sms <= 0) sms = 148;
    cudaFuncSetAttribute(k_main, cudaFuncAttributeMaxDynamicSharedMemorySize, S_TOT * 4);

    k_prep<<<PREPB, 1024>>>(edge_types, nodes, ho_params, out);
    k_main<<<sms, NTHR, S_TOT * 4>>>(bp_params, bp_bias, ho_bias, edges, edge_types, out);
}